// round 1
// baseline (speedup 1.0000x reference)
#include <cuda_runtime.h>
#include <cstdint>
#include <cstddef>

// Problem constants
#define Gc 64
#define NODESc 511
#define Nc 512          // NODES + 1 (graph token at position 0)
#define Hc 768
#define Ec 4096
#define Mc (Gc * Nc)    // 32768 total rows

// Scratch (device globals; no allocation allowed)
__device__ float g_agg[(size_t)Mc * Hc];   // 96 MiB neighbor-sum accumulator
__device__ float g_invdeg[Mc];
__device__ int   g_deg[Mc];

// ---------------------------------------------------------------------------
// Kernel 1: zero agg + deg
// grid = Mc*Hc/4/1024 = 6144 blocks x 1024 threads, one float4 per thread
// ---------------------------------------------------------------------------
__global__ void zero_kernel() {
    size_t i = (size_t)blockIdx.x * blockDim.x + threadIdx.x;
    reinterpret_cast<float4*>(g_agg)[i] = make_float4(0.f, 0.f, 0.f, 0.f);
    if (i < (size_t)Mc) g_deg[i] = 0;
}

// ---------------------------------------------------------------------------
// Kernel 2: gather node features -> d_out part 1 (x)
// x[g][0][:] = graph_emb; x[g][i][:] = node_emb[input_nodes[g][i-1]]
// one block (192 threads, H/4 float4s) per row
// ---------------------------------------------------------------------------
__global__ void gather_kernel(const int* __restrict__ nodes,
                              const float* __restrict__ node_emb,
                              const float* __restrict__ graph_emb,
                              float* __restrict__ x) {
    int row = blockIdx.x;
    int g = row >> 9;        // / 512
    int i = row & 511;
    const float4* s4;
    if (i == 0) {
        s4 = reinterpret_cast<const float4*>(graph_emb);
    } else {
        int idx = nodes[g * NODESc + i - 1];
        s4 = reinterpret_cast<const float4*>(node_emb + (size_t)idx * Hc);
    }
    float4* d4 = reinterpret_cast<float4*>(x + (size_t)row * Hc);
    d4[threadIdx.x] = s4[threadIdx.x];
}

// ---------------------------------------------------------------------------
// Kernel 3: edge aggregation. One warp per edge.
//   agg[g, dst, :] += x[g, src, :]    (red.global.add.v4.f32)
//   deg[g, dst]    += 1
// ---------------------------------------------------------------------------
__global__ void agg_kernel(const int* __restrict__ edges,
                           const float* __restrict__ x) {
    int w    = (blockIdx.x * blockDim.x + threadIdx.x) >> 5;   // global warp id
    int lane = threadIdx.x & 31;
    int g = w >> 12;        // / 4096 edges per graph
    int e = w & 4095;
    const int* eg = edges + (size_t)g * 2 * Ec;
    int src = eg[e];
    int dst = eg[Ec + e];
    if (lane == 0) atomicAdd(&g_deg[g * Nc + dst], 1);
    const float4* xs = reinterpret_cast<const float4*>(x + ((size_t)g * Nc + src) * Hc);
    float* ab = g_agg + ((size_t)g * Nc + dst) * Hc;
    #pragma unroll
    for (int t = lane; t < Hc / 4; t += 32) {
        float4 v = xs[t];
        asm volatile("red.global.add.v4.f32 [%0], {%1,%2,%3,%4};"
                     :: "l"(ab + 4 * t), "f"(v.x), "f"(v.y), "f"(v.z), "f"(v.w)
                     : "memory");
    }
}

// ---------------------------------------------------------------------------
// Kernel 4: invdeg[m] = 1 / max(deg[m], 1)
// ---------------------------------------------------------------------------
__global__ void invdeg_kernel() {
    int i = blockIdx.x * blockDim.x + threadIdx.x;
    int d = g_deg[i];
    g_invdeg[i] = 1.0f / (float)(d > 1 ? d : 1);
}

// ---------------------------------------------------------------------------
// Kernel 5: fused SGEMM
//   out2[m, n] = sum_k (agg[m,k]*invdeg[m]) * Wl[n,k]
//              + sum_k x[m,k] * Wr[n,k]  + bl[n]
// Treated as M=32768, N=768, K=1536 GEMM with virtual K-concat.
// Tiles: BM=128, BN=128, BK=16; 256 threads, 8x8 per thread.
// All dims divide evenly -> no bounds checks.
// ---------------------------------------------------------------------------
__global__ __launch_bounds__(256) void gemm_kernel(
    const float* __restrict__ x,
    const float* __restrict__ Wl,
    const float* __restrict__ Wr,
    const float* __restrict__ bl,
    float* __restrict__ out) {
    __shared__ float As[16][136];   // [k][m], padded
    __shared__ float Bs[16][136];   // [k][n], padded

    const int tid = threadIdx.x;
    const int m0 = blockIdx.y * 128;
    const int n0 = blockIdx.x * 128;

    const int tm = (tid >> 4) << 3;   // 0..120
    const int tn = (tid & 15) << 3;   // 0..120

    const int lrow = tid >> 2;        // 0..63 (row within tile, +64 for 2nd load)
    const int lkq  = (tid & 3) * 4;   // k-quad offset: 0,4,8,12

    float acc[8][8];
    #pragma unroll
    for (int i = 0; i < 8; ++i)
        #pragma unroll
        for (int j = 0; j < 8; ++j) acc[i][j] = 0.f;

    for (int kt = 0; kt < 96; ++kt) {
        const int k0 = kt * 16;
        const float* Aglob;
        const float* Wglob;
        int kk;
        bool scale;
        if (k0 < Hc) { Aglob = g_agg; Wglob = Wl; kk = k0;       scale = true;  }
        else         { Aglob = x;     Wglob = Wr; kk = k0 - Hc;  scale = false; }

        #pragma unroll
        for (int l = 0; l < 2; ++l) {
            int row = lrow + l * 64;
            float4 a = *reinterpret_cast<const float4*>(
                Aglob + (size_t)(m0 + row) * Hc + kk + lkq);
            if (scale) {
                float s = g_invdeg[m0 + row];
                a.x *= s; a.y *= s; a.z *= s; a.w *= s;
            }
            As[lkq + 0][row] = a.x;
            As[lkq + 1][row] = a.y;
            As[lkq + 2][row] = a.z;
            As[lkq + 3][row] = a.w;

            float4 b = *reinterpret_cast<const float4*>(
                Wglob + (size_t)(n0 + row) * Hc + kk + lkq);
            Bs[lkq + 0][row] = b.x;
            Bs[lkq + 1][row] = b.y;
            Bs[lkq + 2][row] = b.z;
            Bs[lkq + 3][row] = b.w;
        }
        __syncthreads();

        #pragma unroll
        for (int k = 0; k < 16; ++k) {
            float4 a0 = *reinterpret_cast<const float4*>(&As[k][tm]);
            float4 a1 = *reinterpret_cast<const float4*>(&As[k][tm + 4]);
            float4 b0 = *reinterpret_cast<const float4*>(&Bs[k][tn]);
            float4 b1 = *reinterpret_cast<const float4*>(&Bs[k][tn + 4]);
            float ar[8] = {a0.x, a0.y, a0.z, a0.w, a1.x, a1.y, a1.z, a1.w};
            float br[8] = {b0.x, b0.y, b0.z, b0.w, b1.x, b1.y, b1.z, b1.w};
            #pragma unroll
            for (int i = 0; i < 8; ++i)
                #pragma unroll
                for (int j = 0; j < 8; ++j)
                    acc[i][j] = fmaf(ar[i], br[j], acc[i][j]);
        }
        __syncthreads();
    }

    // Epilogue: add bias, write float4s
    #pragma unroll
    for (int i = 0; i < 8; ++i) {
        size_t mrow = (size_t)(m0 + tm + i) * Hc;
        #pragma unroll
        for (int j = 0; j < 8; j += 4) {
            int n = n0 + tn + j;
            float4 v;
            v.x = acc[i][j + 0] + bl[n + 0];
            v.y = acc[i][j + 1] + bl[n + 1];
            v.z = acc[i][j + 2] + bl[n + 2];
            v.w = acc[i][j + 3] + bl[n + 3];
            *reinterpret_cast<float4*>(out + mrow + n) = v;
        }
    }
}

// ---------------------------------------------------------------------------
// Launch
// Input order (metadata): input_nodes(i32), input_edges(i32), node_emb(f32),
//                         graph_emb(f32), W_l(f32), b_l(f32), W_r(f32)
// d_out: [graph_node_feature | graph_edge_feature], each Mc*Hc floats
// ---------------------------------------------------------------------------
extern "C" void kernel_launch(void* const* d_in, const int* in_sizes, int n_in,
                              void* d_out, int out_size) {
    const int*   nodes     = (const int*)d_in[0];
    const int*   edges     = (const int*)d_in[1];
    const float* node_emb  = (const float*)d_in[2];
    const float* graph_emb = (const float*)d_in[3];
    const float* Wl        = (const float*)d_in[4];
    const float* bl        = (const float*)d_in[5];
    const float* Wr        = (const float*)d_in[6];

    float* out1 = (float*)d_out;                    // graph_node_feature
    float* out2 = out1 + (size_t)Mc * Hc;           // graph_edge_feature

    zero_kernel<<<((size_t)Mc * Hc / 4) / 1024, 1024>>>();
    gather_kernel<<<Mc, Hc / 4>>>(nodes, node_emb, graph_emb, out1);
    agg_kernel<<<(Gc * Ec) / 8, 256>>>(edges, out1);   // 8 warps/block, 1 edge/warp
    invdeg_kernel<<<Mc / 1024, 1024>>>();
    gemm_kernel<<<dim3(Hc / 128, Mc / 128), 256>>>(out1, Wl, Wr, bl, out2);
}

// round 3
// speedup vs baseline: 40.2021x; 40.2021x over previous
#include <cuda_runtime.h>
#include <cstdint>
#include <cstddef>

// Problem constants
#define Gc 64
#define NODESc 511
#define Nc 512          // NODES + 1 (graph token at row 0 of each graph)
#define Hc 768
#define Ec 4096
#define Mc (Gc * Nc)    // 32768 rows
#define NT 5            // distinct source vectors: node_emb[0..3], graph_emb (t=4)

// Scratch (device globals; allocation is forbidden)
__device__ int   g_cnt[Mc * NT];     // per-dst-row counts of source types
__device__ float g_Q[NT * Hc];       // emb5 @ W_l^T
__device__ float g_P[NT * Hc];       // emb5 @ W_r^T

// ---------------------------------------------------------------------------
// Kernel 1: zero the count matrix
// ---------------------------------------------------------------------------
__global__ void zero_kernel() {
    int i = blockIdx.x * blockDim.x + threadIdx.x;   // grid covers Mc*NT exactly
    g_cnt[i] = 0;
}

// ---------------------------------------------------------------------------
// Kernel 2: edge counting.  One thread per edge:
//   t = type(src) ; cnt[g, dst, t] += 1
// type(src) = 4 if src==0 (graph token) else input_nodes[g][src-1]
// ---------------------------------------------------------------------------
__global__ void count_kernel(const int* __restrict__ edges,
                             const int* __restrict__ nodes) {
    int e = blockIdx.x * blockDim.x + threadIdx.x;   // 0 .. G*E-1
    int g  = e >> 12;           // / 4096
    int ei = e & 4095;
    const int* eg = edges + (size_t)g * 2 * Ec;
    int src = eg[ei];
    int dst = eg[Ec + ei];
    int t = (src == 0) ? 4 : nodes[g * NODESc + src - 1];
    atomicAdd(&g_cnt[(g * Nc + dst) * NT + t], 1);
}

// ---------------------------------------------------------------------------
// Kernel 3: tiny projections  Q = emb5 @ W_l^T,  P = emb5 @ W_r^T
// One block per output column n; warp 0 -> W_l, warp 1 -> W_r.
// Each lane accumulates 5 partial dots (one per source type), warp-reduce.
// ---------------------------------------------------------------------------
__global__ void qp_kernel(const float* __restrict__ node_emb,
                          const float* __restrict__ graph_emb,
                          const float* __restrict__ Wl,
                          const float* __restrict__ Wr) {
    int n    = blockIdx.x;
    int w    = threadIdx.x >> 5;     // 0: Wl/Q, 1: Wr/P
    int lane = threadIdx.x & 31;

    const float4* Wrow = reinterpret_cast<const float4*>((w ? Wr : Wl) + (size_t)n * Hc);
    const float4* e4[NT];
    #pragma unroll
    for (int t = 0; t < 4; ++t)
        e4[t] = reinterpret_cast<const float4*>(node_emb + (size_t)t * Hc);
    e4[4] = reinterpret_cast<const float4*>(graph_emb);

    float acc[NT] = {0.f, 0.f, 0.f, 0.f, 0.f};
    #pragma unroll
    for (int k4 = lane; k4 < Hc / 4; k4 += 32) {
        float4 wv = Wrow[k4];
        #pragma unroll
        for (int t = 0; t < NT; ++t) {
            float4 ev = e4[t][k4];
            acc[t] = fmaf(ev.x, wv.x,
                     fmaf(ev.y, wv.y,
                     fmaf(ev.z, wv.z,
                     fmaf(ev.w, wv.w, acc[t]))));
        }
    }
    #pragma unroll
    for (int t = 0; t < NT; ++t)
        #pragma unroll
        for (int off = 16; off; off >>= 1)
            acc[t] += __shfl_xor_sync(0xffffffffu, acc[t], off);

    if (lane == 0) {
        float* dst = w ? g_P : g_Q;
        #pragma unroll
        for (int t = 0; t < NT; ++t)
            dst[t * Hc + n] = acc[t];
    }
}

// ---------------------------------------------------------------------------
// Kernel 4: fused gather + output.  One block (192 threads) per row m.
//   out1[m] = emb5[type(m)]
//   out2[m][n] = invdeg[m] * sum_t cnt[m][t] * Q[t][n]  +  P[type(m)][n] + bl[n]
// All tables (Q, P, bl, emb5 ~ 48 KB) are L2/L1 resident; write-bound kernel.
// ---------------------------------------------------------------------------
__global__ __launch_bounds__(192) void out_kernel(
    const int* __restrict__ nodes,
    const float* __restrict__ node_emb,
    const float* __restrict__ graph_emb,
    const float* __restrict__ bl,
    float* __restrict__ out1,
    float* __restrict__ out2) {
    int row = blockIdx.x;
    int g = row >> 9;
    int i = row & 511;

    // row type + counts (broadcast loads, cheap)
    int trow = (i == 0) ? 4 : __ldg(nodes + g * NODESc + i - 1);
    const int* cp = g_cnt + (size_t)row * NT;
    float c0 = (float)__ldg(cp + 0);
    float c1 = (float)__ldg(cp + 1);
    float c2 = (float)__ldg(cp + 2);
    float c3 = (float)__ldg(cp + 3);
    float c4 = (float)__ldg(cp + 4);
    float deg = c0 + c1 + c2 + c3 + c4;
    float inv = 1.0f / fmaxf(deg, 1.0f);
    c0 *= inv; c1 *= inv; c2 *= inv; c3 *= inv; c4 *= inv;

    const float4* erow = (trow < 4)
        ? reinterpret_cast<const float4*>(node_emb + (size_t)trow * Hc)
        : reinterpret_cast<const float4*>(graph_emb);

    int n4 = threadIdx.x;            // 0..191, covers 768 floats

    // out1: copy source vector
    reinterpret_cast<float4*>(out1 + (size_t)row * Hc)[n4] = erow[n4];

    // out2
    const float4* q0 = reinterpret_cast<const float4*>(g_Q + 0 * Hc);
    const float4* q1 = reinterpret_cast<const float4*>(g_Q + 1 * Hc);
    const float4* q2 = reinterpret_cast<const float4*>(g_Q + 2 * Hc);
    const float4* q3 = reinterpret_cast<const float4*>(g_Q + 3 * Hc);
    const float4* q4 = reinterpret_cast<const float4*>(g_Q + 4 * Hc);
    const float4* pp = reinterpret_cast<const float4*>(g_P + (size_t)trow * Hc);
    const float4* b4 = reinterpret_cast<const float4*>(bl);

    float4 v0 = q0[n4], v1 = q1[n4], v2 = q2[n4], v3 = q3[n4], v4 = q4[n4];
    float4 pv = pp[n4], bv = b4[n4];

    float4 o;
    o.x = fmaf(c0, v0.x, fmaf(c1, v1.x, fmaf(c2, v2.x, fmaf(c3, v3.x, fmaf(c4, v4.x, pv.x + bv.x)))));
    o.y = fmaf(c0, v0.y, fmaf(c1, v1.y, fmaf(c2, v2.y, fmaf(c3, v3.y, fmaf(c4, v4.y, pv.y + bv.y)))));
    o.z = fmaf(c0, v0.z, fmaf(c1, v1.z, fmaf(c2, v2.z, fmaf(c3, v3.z, fmaf(c4, v4.z, pv.z + bv.z)))));
    o.w = fmaf(c0, v0.w, fmaf(c1, v1.w, fmaf(c2, v2.w, fmaf(c3, v3.w, fmaf(c4, v4.w, pv.w + bv.w)))));
    reinterpret_cast<float4*>(out2 + (size_t)row * Hc)[n4] = o;
}

// ---------------------------------------------------------------------------
// Launch. Inputs: input_nodes(i32), input_edges(i32), node_emb(f32),
//                 graph_emb(f32), W_l(f32), b_l(f32), W_r(f32)
// d_out: [graph_node_feature | graph_edge_feature]
// ---------------------------------------------------------------------------
extern "C" void kernel_launch(void* const* d_in, const int* in_sizes, int n_in,
                              void* d_out, int out_size) {
    const int*   nodes     = (const int*)d_in[0];
    const int*   edges     = (const int*)d_in[1];
    const float* node_emb  = (const float*)d_in[2];
    const float* graph_emb = (const float*)d_in[3];
    const float* Wl        = (const float*)d_in[4];
    const float* bl        = (const float*)d_in[5];
    const float* Wr        = (const float*)d_in[6];

    float* out1 = (float*)d_out;
    float* out2 = out1 + (size_t)Mc * Hc;

    zero_kernel<<<(Mc * NT) / 1024, 1024>>>();                 // 160 blocks
    count_kernel<<<(Gc * Ec) / 256, 256>>>(edges, nodes);      // 1024 blocks
    qp_kernel<<<Hc, 64>>>(node_emb, graph_emb, Wl, Wr);        // 768 blocks
    out_kernel<<<Mc, Hc / 4>>>(nodes, node_emb, graph_emb, bl, out1, out2);
}

// round 4
// speedup vs baseline: 54.0788x; 1.3452x over previous
#include <cuda_runtime.h>
#include <cstdint>
#include <cstddef>

// Problem constants
#define Gc 64
#define NODESc 511
#define Nc 512          // NODES + 1 (graph token at row 0 of each graph)
#define Hc 768
#define Ec 4096
#define Mc (Gc * Nc)    // 32768 rows
#define NT 5            // distinct source vectors: node_emb[0..3], graph_emb (t=4)
#define RPB 8           // rows per block in out_kernel

// Scratch (device globals; allocation is forbidden)
__device__ int   g_cnt[Mc * NT];     // per-dst-row counts of source types
__device__ float g_Q[NT * Hc];       // emb5 @ W_l^T
__device__ float g_Pb[NT * Hc];      // emb5 @ W_r^T + b_l  (bias folded in)

// ---------------------------------------------------------------------------
// Kernel 1 (fused): blocks [0,160) zero the count matrix;
//                   blocks [160,928) compute Q and Pb columns.
// blockDim = 64.
// ---------------------------------------------------------------------------
__global__ __launch_bounds__(64) void init_kernel(
    const float* __restrict__ node_emb,
    const float* __restrict__ graph_emb,
    const float* __restrict__ Wl,
    const float* __restrict__ Wr,
    const float* __restrict__ bl) {
    if (blockIdx.x < 160) {
        // zero g_cnt: 160 blocks * 64 threads * 4 int4 = 163840 ints
        int base = (blockIdx.x * 64 + threadIdx.x) * 4;
        int4* p = reinterpret_cast<int4*>(g_cnt);
        #pragma unroll
        for (int q = 0; q < 4; ++q)
            p[base / 4 + q * 10240] = make_int4(0, 0, 0, 0);
        return;
    }
    int n    = blockIdx.x - 160;     // output column 0..767
    int w    = threadIdx.x >> 5;     // 0: Wl/Q, 1: Wr/Pb
    int lane = threadIdx.x & 31;

    const float4* Wrow = reinterpret_cast<const float4*>((w ? Wr : Wl) + (size_t)n * Hc);
    const float4* e4[NT];
    #pragma unroll
    for (int t = 0; t < 4; ++t)
        e4[t] = reinterpret_cast<const float4*>(node_emb + (size_t)t * Hc);
    e4[4] = reinterpret_cast<const float4*>(graph_emb);

    float acc[NT] = {0.f, 0.f, 0.f, 0.f, 0.f};
    #pragma unroll
    for (int k4 = lane; k4 < Hc / 4; k4 += 32) {
        float4 wv = Wrow[k4];
        #pragma unroll
        for (int t = 0; t < NT; ++t) {
            float4 ev = e4[t][k4];
            acc[t] = fmaf(ev.x, wv.x,
                     fmaf(ev.y, wv.y,
                     fmaf(ev.z, wv.z,
                     fmaf(ev.w, wv.w, acc[t]))));
        }
    }
    #pragma unroll
    for (int t = 0; t < NT; ++t)
        #pragma unroll
        for (int off = 16; off; off >>= 1)
            acc[t] += __shfl_xor_sync(0xffffffffu, acc[t], off);

    if (lane == 0) {
        float* dst = w ? g_Pb : g_Q;
        float badd = w ? bl[n] : 0.f;
        #pragma unroll
        for (int t = 0; t < NT; ++t)
            dst[t * Hc + n] = acc[t] + badd;
    }
}

// ---------------------------------------------------------------------------
// Kernel 2: edge counting. One thread per edge:
//   t = type(src) ; cnt[g, dst, t] += 1
// type(src) = 4 if src==0 (graph token) else input_nodes[g][src-1]
// ---------------------------------------------------------------------------
__global__ void count_kernel(const int* __restrict__ edges,
                             const int* __restrict__ nodes) {
    int e = blockIdx.x * blockDim.x + threadIdx.x;   // 0 .. G*E-1
    int g  = e >> 12;           // / 4096
    int ei = e & 4095;
    const int* eg = edges + (size_t)g * 2 * Ec;
    int src = eg[ei];
    int dst = eg[Ec + ei];
    int t = (src == 0) ? 4 : nodes[g * NODESc + src - 1];
    atomicAdd(&g_cnt[(g * Nc + dst) * NT + t], 1);
}

// ---------------------------------------------------------------------------
// Kernel 3: fused gather + output, register-resident tables.
// Thread owns column quad n4; processes RPB consecutive rows.
//   out1[m] = emb5[type(m)]
//   out2[m][n] = sum_t (cnt[m][t]/deg) * Q[t][n] + Pb[type(m)][n]
// Per-row memory ops: 6 broadcast scalar loads + 2 streaming STG.128.
// ---------------------------------------------------------------------------
__device__ __forceinline__ float4 sel5(const float4 v[NT], int t) {
    float4 r = v[0];
    r = (t == 1) ? v[1] : r;
    r = (t == 2) ? v[2] : r;
    r = (t == 3) ? v[3] : r;
    r = (t == 4) ? v[4] : r;
    return r;
}

__global__ __launch_bounds__(192) void out_kernel(
    const int* __restrict__ nodes,
    const float* __restrict__ node_emb,
    const float* __restrict__ graph_emb,
    float* __restrict__ out1,
    float* __restrict__ out2) {
    const int n4 = threadIdx.x;      // 0..191 column quad

    // Load tables into registers once (L1/L2-resident, 15 LDG.128 total)
    float4 Q[NT], Pb[NT], Eb[NT];
    #pragma unroll
    for (int t = 0; t < NT; ++t) {
        Q[t]  = reinterpret_cast<const float4*>(g_Q  + (size_t)t * Hc)[n4];
        Pb[t] = reinterpret_cast<const float4*>(g_Pb + (size_t)t * Hc)[n4];
    }
    #pragma unroll
    for (int t = 0; t < 4; ++t)
        Eb[t] = reinterpret_cast<const float4*>(node_emb + (size_t)t * Hc)[n4];
    Eb[4] = reinterpret_cast<const float4*>(graph_emb)[n4];

    const int row0 = blockIdx.x * RPB;
    #pragma unroll
    for (int r = 0; r < RPB; ++r) {
        int row = row0 + r;
        int g = row >> 9;
        int i = row & 511;
        int trow = (i == 0) ? 4 : __ldg(nodes + g * NODESc + i - 1);
        const int* cp = g_cnt + (size_t)row * NT;
        float c0 = (float)__ldg(cp + 0);
        float c1 = (float)__ldg(cp + 1);
        float c2 = (float)__ldg(cp + 2);
        float c3 = (float)__ldg(cp + 3);
        float c4 = (float)__ldg(cp + 4);
        float deg = c0 + c1 + c2 + c3 + c4;
        float inv = 1.0f / fmaxf(deg, 1.0f);
        c0 *= inv; c1 *= inv; c2 *= inv; c3 *= inv; c4 *= inv;

        float4 o1 = sel5(Eb, trow);
        float4 o2 = sel5(Pb, trow);
        o2.x = fmaf(c0, Q[0].x, fmaf(c1, Q[1].x, fmaf(c2, Q[2].x, fmaf(c3, Q[3].x, fmaf(c4, Q[4].x, o2.x)))));
        o2.y = fmaf(c0, Q[0].y, fmaf(c1, Q[1].y, fmaf(c2, Q[2].y, fmaf(c3, Q[3].y, fmaf(c4, Q[4].y, o2.y)))));
        o2.z = fmaf(c0, Q[0].z, fmaf(c1, Q[1].z, fmaf(c2, Q[2].z, fmaf(c3, Q[3].z, fmaf(c4, Q[4].z, o2.z)))));
        o2.w = fmaf(c0, Q[0].w, fmaf(c1, Q[1].w, fmaf(c2, Q[2].w, fmaf(c3, Q[3].w, fmaf(c4, Q[4].w, o2.w)))));

        __stcs(reinterpret_cast<float4*>(out1 + (size_t)row * Hc) + n4, o1);
        __stcs(reinterpret_cast<float4*>(out2 + (size_t)row * Hc) + n4, o2);
    }
}

// ---------------------------------------------------------------------------
// Launch. Inputs: input_nodes(i32), input_edges(i32), node_emb(f32),
//                 graph_emb(f32), W_l(f32), b_l(f32), W_r(f32)
// d_out: [graph_node_feature | graph_edge_feature]
// ---------------------------------------------------------------------------
extern "C" void kernel_launch(void* const* d_in, const int* in_sizes, int n_in,
                              void* d_out, int out_size) {
    const int*   nodes     = (const int*)d_in[0];
    const int*   edges     = (const int*)d_in[1];
    const float* node_emb  = (const float*)d_in[2];
    const float* graph_emb = (const float*)d_in[3];
    const float* Wl        = (const float*)d_in[4];
    const float* bl        = (const float*)d_in[5];
    const float* Wr        = (const float*)d_in[6];

    float* out1 = (float*)d_out;
    float* out2 = out1 + (size_t)Mc * Hc;

    init_kernel<<<160 + Hc, 64>>>(node_emb, graph_emb, Wl, Wr, bl);
    count_kernel<<<(Gc * Ec) / 256, 256>>>(edges, nodes);
    out_kernel<<<Mc / RPB, Hc / 4>>>(nodes, node_emb, graph_emb, out1, out2);
}

// round 5
// speedup vs baseline: 56.7981x; 1.0503x over previous
#include <cuda_runtime.h>
#include <cstdint>
#include <cstddef>

// Problem constants
#define Gc 64
#define NODESc 511
#define Nc 512          // NODES + 1 (graph token at row 0 of each graph)
#define Hc 768
#define Ec 4096
#define Mc (Gc * Nc)    // 32768 rows
#define NT 5            // distinct source vectors: node_emb[0..3], graph_emb (t=4)
#define RPB 8           // rows per block in out_kernel

// Scratch (device globals; allocation is forbidden)
__device__ int   g_cnt[Mc * NT];     // per-dst-row counts of source types
__device__ float g_Q[NT * Hc];       // emb5 @ W_l^T
__device__ float g_Pb[NT * Hc];      // emb5 @ W_r^T + b_l  (bias folded in)

// ---------------------------------------------------------------------------
// Kernel 1 (fused front end), blockDim = 256:
//   blocks [0, 64):       per-graph edge counting in shared memory
//   blocks [64, 64+192):  Q/Pb projection, one warp per (matrix, column)
// ---------------------------------------------------------------------------
__global__ __launch_bounds__(256) void front_kernel(
    const int* __restrict__ nodes,
    const int* __restrict__ edges,
    const float* __restrict__ node_emb,
    const float* __restrict__ graph_emb,
    const float* __restrict__ Wl,
    const float* __restrict__ Wr,
    const float* __restrict__ bl) {
    __shared__ int scnt[Nc * NT];    // 10 KB counters
    __shared__ int stype[Nc];        // type per node row (row 0 -> 4)

    const int tid = threadIdx.x;

    if (blockIdx.x < Gc) {
        // ---- per-graph counting ----
        const int g = blockIdx.x;

        // zero counters
        #pragma unroll
        for (int i = tid; i < Nc * NT; i += 256) scnt[i] = 0;
        // cache node types
        if (tid == 0) stype[0] = 4;
        for (int i = tid; i < NODESc; i += 256)
            stype[i + 1] = __ldg(nodes + g * NODESc + i);
        __syncthreads();

        const int* eg = edges + (size_t)g * 2 * Ec;
        #pragma unroll
        for (int e = tid; e < Ec; e += 256) {
            int src = __ldg(eg + e);
            int dst = __ldg(eg + Ec + e);
            atomicAdd(&scnt[dst * NT + stype[src]], 1);
        }
        __syncthreads();

        // coalesced dump: 2560 ints = 640 int4
        int4* dst4 = reinterpret_cast<int4*>(g_cnt + (size_t)g * Nc * NT);
        const int4* src4 = reinterpret_cast<const int4*>(scnt);
        #pragma unroll
        for (int i = tid; i < (Nc * NT) / 4; i += 256)
            dst4[i] = src4[i];
        return;
    }

    // ---- Q/Pb projection: warp w handles (matrix = w&1, column n = w>>1) ----
    const int wglob = (blockIdx.x - Gc) * 8 + (tid >> 5);   // 0..1535
    const int lane  = tid & 31;
    const int mtx   = wglob & 1;        // 0: Wl -> Q, 1: Wr -> Pb
    const int n     = wglob >> 1;       // 0..767

    const float4* Wrow = reinterpret_cast<const float4*>((mtx ? Wr : Wl) + (size_t)n * Hc);
    const float4* e4[NT];
    #pragma unroll
    for (int t = 0; t < 4; ++t)
        e4[t] = reinterpret_cast<const float4*>(node_emb + (size_t)t * Hc);
    e4[4] = reinterpret_cast<const float4*>(graph_emb);

    float acc[NT] = {0.f, 0.f, 0.f, 0.f, 0.f};
    #pragma unroll
    for (int k4 = lane; k4 < Hc / 4; k4 += 32) {
        float4 wv = Wrow[k4];
        #pragma unroll
        for (int t = 0; t < NT; ++t) {
            float4 ev = e4[t][k4];
            acc[t] = fmaf(ev.x, wv.x,
                     fmaf(ev.y, wv.y,
                     fmaf(ev.z, wv.z,
                     fmaf(ev.w, wv.w, acc[t]))));
        }
    }
    #pragma unroll
    for (int t = 0; t < NT; ++t)
        #pragma unroll
        for (int off = 16; off; off >>= 1)
            acc[t] += __shfl_xor_sync(0xffffffffu, acc[t], off);

    if (lane == 0) {
        float* dst = mtx ? g_Pb : g_Q;
        float badd = mtx ? __ldg(bl + n) : 0.f;
        #pragma unroll
        for (int t = 0; t < NT; ++t)
            dst[t * Hc + n] = acc[t] + badd;
    }
}

// ---------------------------------------------------------------------------
// Kernel 2: fused gather + output, register-resident tables.
// Thread owns column quad n4; processes RPB consecutive rows.
//   out1[m] = emb5[type(m)]
//   out2[m][n] = sum_t (cnt[m][t]/deg) * Q[t][n] + Pb[type(m)][n]
// ---------------------------------------------------------------------------
__device__ __forceinline__ float4 sel5(const float4 v[NT], int t) {
    float4 r = v[0];
    r = (t == 1) ? v[1] : r;
    r = (t == 2) ? v[2] : r;
    r = (t == 3) ? v[3] : r;
    r = (t == 4) ? v[4] : r;
    return r;
}

__global__ __launch_bounds__(192) void out_kernel(
    const int* __restrict__ nodes,
    const float* __restrict__ node_emb,
    const float* __restrict__ graph_emb,
    float* __restrict__ out1,
    float* __restrict__ out2) {
    const int n4 = threadIdx.x;      // 0..191 column quad

    // Load tables into registers once (L1/L2-resident, 15 LDG.128 total)
    float4 Q[NT], Pb[NT], Eb[NT];
    #pragma unroll
    for (int t = 0; t < NT; ++t) {
        Q[t]  = reinterpret_cast<const float4*>(g_Q  + (size_t)t * Hc)[n4];
        Pb[t] = reinterpret_cast<const float4*>(g_Pb + (size_t)t * Hc)[n4];
    }
    #pragma unroll
    for (int t = 0; t < 4; ++t)
        Eb[t] = reinterpret_cast<const float4*>(node_emb + (size_t)t * Hc)[n4];
    Eb[4] = reinterpret_cast<const float4*>(graph_emb)[n4];

    const int row0 = blockIdx.x * RPB;
    #pragma unroll
    for (int r = 0; r < RPB; ++r) {
        int row = row0 + r;
        int g = row >> 9;
        int i = row & 511;
        int trow = (i == 0) ? 4 : __ldg(nodes + g * NODESc + i - 1);
        const int* cp = g_cnt + (size_t)row * NT;
        float c0 = (float)__ldg(cp + 0);
        float c1 = (float)__ldg(cp + 1);
        float c2 = (float)__ldg(cp + 2);
        float c3 = (float)__ldg(cp + 3);
        float c4 = (float)__ldg(cp + 4);
        float deg = c0 + c1 + c2 + c3 + c4;
        float inv = 1.0f / fmaxf(deg, 1.0f);
        c0 *= inv; c1 *= inv; c2 *= inv; c3 *= inv; c4 *= inv;

        float4 o1 = sel5(Eb, trow);
        float4 o2 = sel5(Pb, trow);
        o2.x = fmaf(c0, Q[0].x, fmaf(c1, Q[1].x, fmaf(c2, Q[2].x, fmaf(c3, Q[3].x, fmaf(c4, Q[4].x, o2.x)))));
        o2.y = fmaf(c0, Q[0].y, fmaf(c1, Q[1].y, fmaf(c2, Q[2].y, fmaf(c3, Q[3].y, fmaf(c4, Q[4].y, o2.y)))));
        o2.z = fmaf(c0, Q[0].z, fmaf(c1, Q[1].z, fmaf(c2, Q[2].z, fmaf(c3, Q[3].z, fmaf(c4, Q[4].z, o2.z)))));
        o2.w = fmaf(c0, Q[0].w, fmaf(c1, Q[1].w, fmaf(c2, Q[2].w, fmaf(c3, Q[3].w, fmaf(c4, Q[4].w, o2.w)))));

        __stcs(reinterpret_cast<float4*>(out1 + (size_t)row * Hc) + n4, o1);
        __stcs(reinterpret_cast<float4*>(out2 + (size_t)row * Hc) + n4, o2);
    }
}

// ---------------------------------------------------------------------------
// Launch. Inputs: input_nodes(i32), input_edges(i32), node_emb(f32),
//                 graph_emb(f32), W_l(f32), b_l(f32), W_r(f32)
// d_out: [graph_node_feature | graph_edge_feature]
// ---------------------------------------------------------------------------
extern "C" void kernel_launch(void* const* d_in, const int* in_sizes, int n_in,
                              void* d_out, int out_size) {
    const int*   nodes     = (const int*)d_in[0];
    const int*   edges     = (const int*)d_in[1];
    const float* node_emb  = (const float*)d_in[2];
    const float* graph_emb = (const float*)d_in[3];
    const float* Wl        = (const float*)d_in[4];
    const float* bl        = (const float*)d_in[5];
    const float* Wr        = (const float*)d_in[6];

    float* out1 = (float*)d_out;
    float* out2 = out1 + (size_t)Mc * Hc;

    front_kernel<<<Gc + 192, 256>>>(nodes, edges, node_emb, graph_emb, Wl, Wr, bl);
    out_kernel<<<Mc / RPB, Hc / 4>>>(nodes, node_emb, graph_emb, out1, out2);
}

// round 6
// speedup vs baseline: 56.9829x; 1.0033x over previous
#include <cuda_runtime.h>
#include <cstdint>
#include <cstddef>

// Problem constants
#define Gc 64
#define NODESc 511
#define Nc 512          // NODES + 1 (graph token at row 0 of each graph)
#define Hc 768
#define Ec 4096
#define Mc (Gc * Nc)    // 32768 rows
#define NT 5            // distinct source vectors: node_emb[0..3], graph_emb (t=4)
#define RPB 8           // rows per block in out_kernel

// Scratch (device globals; allocation is forbidden)
__device__ int   g_cnt[Mc * NT];     // per-dst-row counts of source types
__device__ float g_Q[NT * Hc];       // emb5 @ W_l^T
__device__ float g_Pb[NT * Hc];      // emb5 @ W_r^T + b_l  (bias folded in)

// ---------------------------------------------------------------------------
// Kernel 1 (fused front end), blockDim = 256:
//   blocks [0, 64):       per-graph edge counting in shared memory
//   blocks [64, 64+192):  Q/Pb projection, one warp per (matrix, column)
// ---------------------------------------------------------------------------
__global__ __launch_bounds__(256) void front_kernel(
    const int* __restrict__ nodes,
    const int* __restrict__ edges,
    const float* __restrict__ node_emb,
    const float* __restrict__ graph_emb,
    const float* __restrict__ Wl,
    const float* __restrict__ Wr,
    const float* __restrict__ bl) {
    __shared__ int scnt[Nc * NT];    // 10 KB counters
    __shared__ int stype[Nc];        // type per node row (row 0 -> 4)

    const int tid = threadIdx.x;

    if (blockIdx.x < Gc) {
        // ---- per-graph counting ----
        const int g = blockIdx.x;

        #pragma unroll
        for (int i = tid; i < Nc * NT; i += 256) scnt[i] = 0;
        if (tid == 0) stype[0] = 4;
        for (int i = tid; i < NODESc; i += 256)
            stype[i + 1] = __ldg(nodes + g * NODESc + i);
        __syncthreads();

        const int* eg = edges + (size_t)g * 2 * Ec;
        #pragma unroll
        for (int e = tid; e < Ec; e += 256) {
            int src = __ldg(eg + e);
            int dst = __ldg(eg + Ec + e);
            atomicAdd(&scnt[dst * NT + stype[src]], 1);
        }
        __syncthreads();

        int4* dst4 = reinterpret_cast<int4*>(g_cnt + (size_t)g * Nc * NT);
        const int4* src4 = reinterpret_cast<const int4*>(scnt);
        #pragma unroll
        for (int i = tid; i < (Nc * NT) / 4; i += 256)
            dst4[i] = src4[i];
        return;
    }

    // ---- Q/Pb projection: warp w handles (matrix = w&1, column n = w>>1) ----
    const int wglob = (blockIdx.x - Gc) * 8 + (tid >> 5);   // 0..1535
    const int lane  = tid & 31;
    const int mtx   = wglob & 1;        // 0: Wl -> Q, 1: Wr -> Pb
    const int n     = wglob >> 1;       // 0..767

    const float4* Wrow = reinterpret_cast<const float4*>((mtx ? Wr : Wl) + (size_t)n * Hc);
    const float4* e4[NT];
    #pragma unroll
    for (int t = 0; t < 4; ++t)
        e4[t] = reinterpret_cast<const float4*>(node_emb + (size_t)t * Hc);
    e4[4] = reinterpret_cast<const float4*>(graph_emb);

    float acc[NT] = {0.f, 0.f, 0.f, 0.f, 0.f};
    #pragma unroll
    for (int k4 = lane; k4 < Hc / 4; k4 += 32) {
        float4 wv = Wrow[k4];
        #pragma unroll
        for (int t = 0; t < NT; ++t) {
            float4 ev = e4[t][k4];
            acc[t] = fmaf(ev.x, wv.x,
                     fmaf(ev.y, wv.y,
                     fmaf(ev.z, wv.z,
                     fmaf(ev.w, wv.w, acc[t]))));
        }
    }
    #pragma unroll
    for (int t = 0; t < NT; ++t)
        #pragma unroll
        for (int off = 16; off; off >>= 1)
            acc[t] += __shfl_xor_sync(0xffffffffu, acc[t], off);

    if (lane == 0) {
        float* dst = mtx ? g_Pb : g_Q;
        float badd = mtx ? __ldg(bl + n) : 0.f;
        #pragma unroll
        for (int t = 0; t < NT; ++t)
            dst[t * Hc + n] = acc[t] + badd;
    }
}

// ---------------------------------------------------------------------------
// Kernel 2: fused gather + output.
//   Q table in registers (used every row); Eb/Pb tables in shared, indexed
//   directly by row type (no predication chains). Per-row scaled counts
//   precomputed once per block into shared.
//   out1[m] = emb5[type(m)]
//   out2[m][n] = sum_t (cnt[m][t]/deg) * Q[t][n] + Pb[type(m)][n]
// ---------------------------------------------------------------------------
__global__ __launch_bounds__(192) void out_kernel(
    const int* __restrict__ nodes,
    const float* __restrict__ node_emb,
    const float* __restrict__ graph_emb,
    float* __restrict__ out1,
    float* __restrict__ out2) {
    __shared__ float4 sEb[NT][192];      // 15 KB
    __shared__ float4 sPb[NT][192];      // 15 KB
    __shared__ float  sC[RPB][NT];       // scaled counts per row
    __shared__ int    sT[RPB];           // row type per row

    const int n4 = threadIdx.x;          // 0..191 column quad
    const int row0 = blockIdx.x * RPB;

    // Stage tables into shared (once per block)
    #pragma unroll
    for (int t = 0; t < NT; ++t)
        sPb[t][n4] = reinterpret_cast<const float4*>(g_Pb + (size_t)t * Hc)[n4];
    #pragma unroll
    for (int t = 0; t < 4; ++t)
        sEb[t][n4] = reinterpret_cast<const float4*>(node_emb + (size_t)t * Hc)[n4];
    sEb[4][n4] = reinterpret_cast<const float4*>(graph_emb)[n4];

    // Q stays in registers (hot every row)
    float4 Q[NT];
    #pragma unroll
    for (int t = 0; t < NT; ++t)
        Q[t] = reinterpret_cast<const float4*>(g_Q + (size_t)t * Hc)[n4];

    // Per-row counts: 8 threads precompute scaled counts + type
    if (n4 < RPB) {
        int row = row0 + n4;
        int g = row >> 9;
        int i = row & 511;
        sT[n4] = (i == 0) ? 4 : __ldg(nodes + g * NODESc + i - 1);
        const int* cp = g_cnt + (size_t)row * NT;
        float c[NT];
        float deg = 0.f;
        #pragma unroll
        for (int t = 0; t < NT; ++t) { c[t] = (float)__ldg(cp + t); deg += c[t]; }
        float inv = 1.0f / fmaxf(deg, 1.0f);
        #pragma unroll
        for (int t = 0; t < NT; ++t) sC[n4][t] = c[t] * inv;
    }
    __syncthreads();

    float4* o1p = reinterpret_cast<float4*>(out1 + (size_t)row0 * Hc) + n4;
    float4* o2p = reinterpret_cast<float4*>(out2 + (size_t)row0 * Hc) + n4;

    #pragma unroll
    for (int r = 0; r < RPB; ++r) {
        int trow = sT[r];
        float c0 = sC[r][0], c1 = sC[r][1], c2 = sC[r][2], c3 = sC[r][3], c4 = sC[r][4];

        float4 o1 = sEb[trow][n4];
        float4 o2 = sPb[trow][n4];
        o2.x = fmaf(c0, Q[0].x, fmaf(c1, Q[1].x, fmaf(c2, Q[2].x, fmaf(c3, Q[3].x, fmaf(c4, Q[4].x, o2.x)))));
        o2.y = fmaf(c0, Q[0].y, fmaf(c1, Q[1].y, fmaf(c2, Q[2].y, fmaf(c3, Q[3].y, fmaf(c4, Q[4].y, o2.y)))));
        o2.z = fmaf(c0, Q[0].z, fmaf(c1, Q[1].z, fmaf(c2, Q[2].z, fmaf(c3, Q[3].z, fmaf(c4, Q[4].z, o2.z)))));
        o2.w = fmaf(c0, Q[0].w, fmaf(c1, Q[1].w, fmaf(c2, Q[2].w, fmaf(c3, Q[3].w, fmaf(c4, Q[4].w, o2.w)))));

        __stcs(o1p, o1);
        __stcs(o2p, o2);
        o1p += Hc / 4;
        o2p += Hc / 4;
    }
}

// ---------------------------------------------------------------------------
// Launch. Inputs: input_nodes(i32), input_edges(i32), node_emb(f32),
//                 graph_emb(f32), W_l(f32), b_l(f32), W_r(f32)
// d_out: [graph_node_feature | graph_edge_feature]
// ---------------------------------------------------------------------------
extern "C" void kernel_launch(void* const* d_in, const int* in_sizes, int n_in,
                              void* d_out, int out_size) {
    const int*   nodes     = (const int*)d_in[0];
    const int*   edges     = (const int*)d_in[1];
    const float* node_emb  = (const float*)d_in[2];
    const float* graph_emb = (const float*)d_in[3];
    const float* Wl        = (const float*)d_in[4];
    const float* bl        = (const float*)d_in[5];
    const float* Wr        = (const float*)d_in[6];

    float* out1 = (float*)d_out;
    float* out2 = out1 + (size_t)Mc * Hc;

    front_kernel<<<Gc + 192, 256>>>(nodes, edges, node_emb, graph_emb, Wl, Wr, bl);
    out_kernel<<<Mc / RPB, Hc / 4>>>(nodes, node_emb, graph_emb, out1, out2);
}